// round 9
// baseline (speedup 1.0000x reference)
#include <cuda_runtime.h>

#define D     4096
#define TPB   128
#define NWARP (TPB / 32)

// Forced re-read (asm volatile so the compiler cannot CSE it with the pass-1
// loads and keep the row live in registers across barriers).
__device__ __forceinline__ float4 reload4(const float4* p) {
    float4 v;
    asm volatile("ld.global.ca.v4.f32 {%0,%1,%2,%3}, [%4];"
                 : "=f"(v.x), "=f"(v.y), "=f"(v.z), "=f"(v.w)
                 : "l"(p));
    return v;
}

// 50-step bisection, fp32 op-for-op identical to the reference trajectory.
// mask = (sum(Z)-1 >= 0). With p = 1/4095, u^p in [0.975, 1] for every
// positive fp32 u, so mask <=> count(Xs_j > t) >= 2, except count==1 where
// sum = powf(u1,p) can round to >= 1.0f only for u1 within ~1e-4 of 1
// (guard at 0.999f, then evaluate the same libdevice powf).
// Early exit: once t = t_min + diff rounds to t_min, rounding monotonicity
// freezes the trajectory and the reference's final t equals t_min.
__device__ __forceinline__ float bisect_t(float Hraw, float Lraw) {
    const float H = __fmul_rn(0.5f, Hraw);   // Xs = 0.5*X, exact & monotone
    const float L = __fmul_rn(0.5f, Lraw);
    const float p = (float)(1.0 / 4095.0);
    float t_min = H - 1.0f;                  // m - 1
    float t_max = H - 0.015625f;             // m - 4096^(1-1.5)
    float diff  = t_max - t_min;
    float t     = t_min;
    #pragma unroll 1
    for (int it = 0; it < 50; it++) {
        diff *= 0.5f;
        t = t_min + diff;
        if (t == t_min) break;               // frozen: final t == t_min
        bool mask;
        if (t < L) {
            mask = true;                     // >=2 positive terms -> sum >= 1.95
        } else {
            float u1 = H - t;
            mask = (u1 >= 0.999f) ? (powf(u1, p) >= 1.0f) : false;
        }
        if (mask) t_min = t;
    }
    return t;
}

__device__ __forceinline__ void fold4(float4 f, float& hi, float& lo) {
    float v;
    v = f.x; lo = fmaxf(lo, fminf(hi, v)); hi = fmaxf(hi, v);
    v = f.y; lo = fmaxf(lo, fminf(hi, v)); hi = fmaxf(hi, v);
    v = f.z; lo = fmaxf(lo, fminf(hi, v)); hi = fmaxf(hi, v);
    v = f.w; lo = fmaxf(lo, fminf(hi, v)); hi = fmaxf(hi, v);
}

__global__ __launch_bounds__(TPB, 16)
void entmax_bisect_kernel(const float* __restrict__ X, float* __restrict__ Y) {
    const int tid  = threadIdx.x;
    const int lane = tid & 31;
    const int wid  = tid >> 5;
    const size_t base = (size_t)blockIdx.x * D;

    __shared__ float s_h[NWARP], s_l[NWARP], s_s[NWARP];
    __shared__ float s_t;

    const float4* Xv = reinterpret_cast<const float4*>(X + base);
    float4*       Yv = reinterpret_cast<float4*>(Y + base);

    // ---- Pass 1: 32 values per thread in two 4xfloat4 batches, fold top-2 ----
    float hi = -3.402823466e38f, lo = -3.402823466e38f;
    {
        float4 f0 = Xv[tid];
        float4 f1 = Xv[TPB + tid];
        float4 f2 = Xv[2 * TPB + tid];
        float4 f3 = Xv[3 * TPB + tid];
        hi = f0.x;
        { float v;
          v = f0.y; lo = fmaxf(lo, fminf(hi, v)); hi = fmaxf(hi, v);
          v = f0.z; lo = fmaxf(lo, fminf(hi, v)); hi = fmaxf(hi, v);
          v = f0.w; lo = fmaxf(lo, fminf(hi, v)); hi = fmaxf(hi, v); }
        fold4(f1, hi, lo);
        fold4(f2, hi, lo);
        fold4(f3, hi, lo);
    }
    {
        float4 f4 = Xv[4 * TPB + tid];
        float4 f5 = Xv[5 * TPB + tid];
        float4 f6 = Xv[6 * TPB + tid];
        float4 f7 = Xv[7 * TPB + tid];
        fold4(f4, hi, lo);
        fold4(f5, hi, lo);
        fold4(f6, hi, lo);
        fold4(f7, hi, lo);
    }
    const float thi = hi;                    // per-thread raw max

    // ---- Warp butterfly top-2 ----
    #pragma unroll
    for (int off = 16; off > 0; off >>= 1) {
        float oh = __shfl_xor_sync(0xffffffffu, hi, off);
        float ol = __shfl_xor_sync(0xffffffffu, lo, off);
        float nh = fmaxf(hi, oh);
        lo = fmaxf(fmaxf(lo, ol), fminf(hi, oh));
        hi = nh;
    }
    if (lane == 0) { s_h[wid] = hi; s_l[wid] = lo; }
    __syncthreads();                                      // b1

    // ---- All threads: combine 4 warps' top-2 (8 LDS, cheap) ----
    float Hb = s_h[0], Lb = s_l[0];
    #pragma unroll
    for (int w = 1; w < NWARP; w++) {
        float oh = s_h[w], ol = s_l[w];
        float nh = fmaxf(Hb, oh);
        Lb = fmaxf(fmaxf(Lb, ol), fminf(Hb, oh));
        Hb = nh;
    }

    // ---- Sure-cold: t_final >= min(Ls, Hs - 0.015625) - 2*diff_final.
    // Threads below that (fat margin) output only zeros; store NOW so the
    // write stream overlaps the bisection bubble. ----
    const float Hs   = __fmul_rn(0.5f, Hb);
    const float Ls   = __fmul_rn(0.5f, Lb);
    const float thr  = fminf(Ls, Hs - 0.015625f) - 2e-5f;
    const float myXs = __fmul_rn(0.5f, thi);
    const bool sure_cold = (myXs < thr);

    const float4 zero4 = make_float4(0.0f, 0.0f, 0.0f, 0.0f);
    if (sure_cold) {
        #pragma unroll
        for (int k = 0; k < 8; k++) __stcs(Yv + k * TPB + tid, zero4);
    }

    // ---- Thread 0: scalar bisection (zero stores above already in flight) ----
    if (tid == 0) s_t = bisect_t(Hb, Lb);
    __syncthreads();                                      // b2

    const float t = s_t;
    const float p = (float)(1.0 / 4095.0);
    const bool hot = (!sure_cold) && (myXs > t);

    // ---- Pass 2 (hot threads, ~1-3 per row): re-read, sum z ----
    float sum = 0.0f;
    if (hot) {
        #pragma unroll
        for (int k = 0; k < 8; k++) {
            float4 g = reload4(Xv + k * TPB + tid);
            float u;
            u = __fmul_rn(0.5f, g.x) - t; if (u > 0.0f) sum += powf(u, p);
            u = __fmul_rn(0.5f, g.y) - t; if (u > 0.0f) sum += powf(u, p);
            u = __fmul_rn(0.5f, g.z) - t; if (u > 0.0f) sum += powf(u, p);
            u = __fmul_rn(0.5f, g.w) - t; if (u > 0.0f) sum += powf(u, p);
        }
    }
    #pragma unroll
    for (int off = 16; off > 0; off >>= 1)
        sum += __shfl_xor_sync(0xffffffffu, sum, off);
    if (lane == 0) s_s[wid] = sum;
    __syncthreads();                                      // b3

    float S = 0.0f;
    #pragma unroll
    for (int w = 0; w < NWARP; w++) S += s_s[w];

    // ---- Epilogue: hot threads write their spans; unsure-cold write zeros ----
    if (hot) {
        const float rinv = 1.0f / S;                      // S > 0 always
        #pragma unroll
        for (int k = 0; k < 8; k++) {
            float4 g = reload4(Xv + k * TPB + tid);       // cache hit
            float4 o = zero4;
            float u;
            u = __fmul_rn(0.5f, g.x) - t; if (u > 0.0f) o.x = powf(u, p) * rinv;
            u = __fmul_rn(0.5f, g.y) - t; if (u > 0.0f) o.y = powf(u, p) * rinv;
            u = __fmul_rn(0.5f, g.z) - t; if (u > 0.0f) o.z = powf(u, p) * rinv;
            u = __fmul_rn(0.5f, g.w) - t; if (u > 0.0f) o.w = powf(u, p) * rinv;
            __stcs(Yv + k * TPB + tid, o);
        }
    } else if (!sure_cold) {
        #pragma unroll
        for (int k = 0; k < 8; k++) __stcs(Yv + k * TPB + tid, zero4);
    }
}

extern "C" void kernel_launch(void* const* d_in, const int* in_sizes, int n_in,
                              void* d_out, int out_size) {
    const float* X = (const float*)d_in[0];
    float* Y = (float*)d_out;
    const int rows = in_sizes[0] / D;                     // 16384
    entmax_bisect_kernel<<<rows, TPB>>>(X, Y);
}

// round 10
// speedup vs baseline: 1.2186x; 1.2186x over previous
#include <cuda_runtime.h>

#define D     4096
#define TPB   256
#define NWARP (TPB / 32)

// Forced re-read (asm volatile so the compiler cannot CSE it with the pass-1
// loads and keep 16 registers alive across barriers).
__device__ __forceinline__ float4 reload4(const float4* p) {
    float4 v;
    asm volatile("ld.global.ca.v4.f32 {%0,%1,%2,%3}, [%4];"
                 : "=f"(v.x), "=f"(v.y), "=f"(v.z), "=f"(v.w)
                 : "l"(p));
    return v;
}

// 50-step bisection, fp32 op-for-op identical to the reference trajectory.
// mask = (sum(Z)-1 >= 0). With p = 1/4095, u^p in [0.975, 1] for every
// positive fp32 u, so mask <=> count(Xs_j > t) >= 2, except count==1 where
// sum = powf(u1,p) can round to >= 1.0f only for u1 within ~1e-4 of 1
// (guard at 0.999f, then evaluate the same libdevice powf).
// Early exit: once t = t_min + diff rounds to t_min, rounding monotonicity
// freezes the trajectory and the reference's final t equals t_min.
__device__ __forceinline__ float bisect_t(float Hraw, float Lraw) {
    const float H = __fmul_rn(0.5f, Hraw);   // Xs = 0.5*X, exact & monotone
    const float L = __fmul_rn(0.5f, Lraw);
    const float p = (float)(1.0 / 4095.0);
    float t_min = H - 1.0f;                  // m - 1
    float t_max = H - 0.015625f;             // m - 4096^(1-1.5)
    float diff  = t_max - t_min;
    float t     = t_min;
    #pragma unroll 1
    for (int it = 0; it < 50; it++) {
        diff *= 0.5f;
        t = t_min + diff;
        if (t == t_min) break;               // frozen: final t == t_min
        bool mask;
        if (t < L) {
            mask = true;                     // >=2 positive terms -> sum >= 1.95
        } else {
            float u1 = H - t;
            mask = (u1 >= 0.999f) ? (powf(u1, p) >= 1.0f) : false;
        }
        if (mask) t_min = t;
    }
    return t;
}

__global__ __launch_bounds__(TPB, 8)
void entmax_bisect_kernel(const float* __restrict__ X, float* __restrict__ Y,
                          int rows) {
    const int tid  = threadIdx.x;
    const int lane = tid & 31;
    const int wid  = tid >> 5;

    __shared__ float s_h[NWARP], s_l[NWARP], s_s[NWARP];
    __shared__ float s_t;

    const float4 zero4 = make_float4(0.0f, 0.0f, 0.0f, 0.0f);

    // Persistent grid-stride: each CTA processes ~rows/gridDim rows, removing
    // wave-transition and CTA launch/retire overhead. Body identical to R6.
    #pragma unroll 1
    for (int r = blockIdx.x; r < rows; r += gridDim.x) {
        const size_t base = (size_t)r * D;
        const float4* Xv = reinterpret_cast<const float4*>(X + base);
        float4*       Yv = reinterpret_cast<float4*>(Y + base);

        // ---- Pass 1: load 16 values, fold into top-2, DROP the values ----
        float hi, lo = -3.402823466e38f;
        {
            float4 f0 = Xv[tid];
            float4 f1 = Xv[TPB + tid];
            float4 f2 = Xv[2 * TPB + tid];
            float4 f3 = Xv[3 * TPB + tid];
            float v;
            hi = f0.x;
            v = f0.y; lo = fmaxf(lo, fminf(hi, v)); hi = fmaxf(hi, v);
            v = f0.z; lo = fmaxf(lo, fminf(hi, v)); hi = fmaxf(hi, v);
            v = f0.w; lo = fmaxf(lo, fminf(hi, v)); hi = fmaxf(hi, v);
            v = f1.x; lo = fmaxf(lo, fminf(hi, v)); hi = fmaxf(hi, v);
            v = f1.y; lo = fmaxf(lo, fminf(hi, v)); hi = fmaxf(hi, v);
            v = f1.z; lo = fmaxf(lo, fminf(hi, v)); hi = fmaxf(hi, v);
            v = f1.w; lo = fmaxf(lo, fminf(hi, v)); hi = fmaxf(hi, v);
            v = f2.x; lo = fmaxf(lo, fminf(hi, v)); hi = fmaxf(hi, v);
            v = f2.y; lo = fmaxf(lo, fminf(hi, v)); hi = fmaxf(hi, v);
            v = f2.z; lo = fmaxf(lo, fminf(hi, v)); hi = fmaxf(hi, v);
            v = f2.w; lo = fmaxf(lo, fminf(hi, v)); hi = fmaxf(hi, v);
            v = f3.x; lo = fmaxf(lo, fminf(hi, v)); hi = fmaxf(hi, v);
            v = f3.y; lo = fmaxf(lo, fminf(hi, v)); hi = fmaxf(hi, v);
            v = f3.z; lo = fmaxf(lo, fminf(hi, v)); hi = fmaxf(hi, v);
            v = f3.w; lo = fmaxf(lo, fminf(hi, v)); hi = fmaxf(hi, v);
        }
        const float thi = hi;                // per-thread raw max

        // ---- Warp butterfly top-2 ----
        #pragma unroll
        for (int off = 16; off > 0; off >>= 1) {
            float oh = __shfl_xor_sync(0xffffffffu, hi, off);
            float ol = __shfl_xor_sync(0xffffffffu, lo, off);
            float nh = fmaxf(hi, oh);
            lo = fmaxf(fmaxf(lo, ol), fminf(hi, oh));
            hi = nh;
        }
        if (lane == 0) { s_h[wid] = hi; s_l[wid] = lo; }
        __syncthreads();                                  // b1

        // ---- All threads: combine 8 warps' top-2 (16 LDS, cheap) ----
        float Hb = s_h[0], Lb = s_l[0];
        #pragma unroll
        for (int w = 1; w < NWARP; w++) {
            float oh = s_h[w], ol = s_l[w];
            float nh = fmaxf(Hb, oh);
            Lb = fmaxf(fmaxf(Lb, ol), fminf(Hb, oh));
            Hb = nh;
        }

        // ---- Sure-cold: t_final >= min(Ls, Hs - 0.015625) - 2*diff_final.
        // Threads below that (fat margin) output only zeros; store NOW so
        // the write stream overlaps the bisection bubble. ----
        const float Hs   = __fmul_rn(0.5f, Hb);
        const float Ls   = __fmul_rn(0.5f, Lb);
        const float thr  = fminf(Ls, Hs - 0.015625f) - 2e-5f;
        const float myXs = __fmul_rn(0.5f, thi);
        const bool sure_cold = (myXs < thr);

        if (sure_cold) {
            __stcs(Yv + tid,           zero4);
            __stcs(Yv + TPB + tid,     zero4);
            __stcs(Yv + 2 * TPB + tid, zero4);
            __stcs(Yv + 3 * TPB + tid, zero4);
        }

        // ---- Thread 0: scalar bisection (zero stores already in flight) ----
        if (tid == 0) s_t = bisect_t(Hb, Lb);
        __syncthreads();                                  // b2

        const float t = s_t;
        const float p = (float)(1.0 / 4095.0);
        const bool hot = (!sure_cold) && (myXs > t);

        // ---- Pass 2 (hot threads, ~1-3 per row): re-read (L1 hit), sum z ----
        float sum = 0.0f;
        if (hot) {
            #pragma unroll
            for (int k = 0; k < 4; k++) {
                float4 g = reload4(Xv + k * TPB + tid);
                float u;
                u = __fmul_rn(0.5f, g.x) - t; if (u > 0.0f) sum += powf(u, p);
                u = __fmul_rn(0.5f, g.y) - t; if (u > 0.0f) sum += powf(u, p);
                u = __fmul_rn(0.5f, g.z) - t; if (u > 0.0f) sum += powf(u, p);
                u = __fmul_rn(0.5f, g.w) - t; if (u > 0.0f) sum += powf(u, p);
            }
        }
        #pragma unroll
        for (int off = 16; off > 0; off >>= 1)
            sum += __shfl_xor_sync(0xffffffffu, sum, off);
        if (lane == 0) s_s[wid] = sum;
        __syncthreads();                                  // b3

        float S = 0.0f;
        #pragma unroll
        for (int w = 0; w < NWARP; w++) S += s_s[w];

        // ---- Epilogue: hot threads write spans; unsure-cold write zeros ----
        if (hot) {
            const float rinv = 1.0f / S;                  // S > 0 always
            #pragma unroll
            for (int k = 0; k < 4; k++) {
                float4 g = reload4(Xv + k * TPB + tid);   // L1 hit
                float4 o = zero4;
                float u;
                u = __fmul_rn(0.5f, g.x) - t; if (u > 0.0f) o.x = powf(u, p) * rinv;
                u = __fmul_rn(0.5f, g.y) - t; if (u > 0.0f) o.y = powf(u, p) * rinv;
                u = __fmul_rn(0.5f, g.z) - t; if (u > 0.0f) o.z = powf(u, p) * rinv;
                u = __fmul_rn(0.5f, g.w) - t; if (u > 0.0f) o.w = powf(u, p) * rinv;
                __stcs(Yv + k * TPB + tid, o);
            }
        } else if (!sure_cold) {
            __stcs(Yv + tid,           zero4);
            __stcs(Yv + TPB + tid,     zero4);
            __stcs(Yv + 2 * TPB + tid, zero4);
            __stcs(Yv + 3 * TPB + tid, zero4);
        }
    }
}

extern "C" void kernel_launch(void* const* d_in, const int* in_sizes, int n_in,
                              void* d_out, int out_size) {
    const float* X = (const float*)d_in[0];
    float* Y = (float*)d_out;
    const int rows = in_sizes[0] / D;                     // 16384
    int grid = 148 * 8;                                   // one persistent wave
    if (grid > rows) grid = rows;
    entmax_bisect_kernel<<<grid, TPB>>>(X, Y, rows);
}

// round 12
// speedup vs baseline: 1.3339x; 1.0947x over previous
#include <cuda_runtime.h>

#define D     4096
#define TPB   256
#define NWARP (TPB / 32)

// Forced re-read (asm volatile so the compiler cannot CSE it with the pass-1
// loads and keep 16 registers alive across barriers).
__device__ __forceinline__ float4 reload4(const float4* p) {
    float4 v;
    asm volatile("ld.global.ca.v4.f32 {%0,%1,%2,%3}, [%4];"
                 : "=f"(v.x), "=f"(v.y), "=f"(v.z), "=f"(v.w)
                 : "l"(p));
    return v;
}

// Exact top-2 merge of two (hi,lo) pairs (handles duplicates correctly):
// merged hi = max(h1,h2); merged lo = max(min(h1,h2), max(l1,l2)).
__device__ __forceinline__ void merge2(float h2, float l2, float& hi, float& lo) {
    float nh = fmaxf(hi, h2);
    lo = fmaxf(fminf(hi, h2), fmaxf(lo, l2));
    hi = nh;
}

// 50-step bisection, fp32 op-for-op identical to the reference trajectory.
// mask = (sum(Z)-1 >= 0). With p = 1/4095, u^p in [0.975, 1] for every
// positive fp32 u, so mask <=> count(Xs_j > t) >= 2, except count==1 where
// sum = powf(u1,p) can round to >= 1.0f only for u1 within ~1e-4 of 1.
// That edge needs u1 = H - t >= 0.999 while t >= L, i.e. H - L >= 0.999;
// when H - L < 0.998 the loop is provably pure "t < L" -> branchless form.
// Early exit: once t = t_min + diff rounds to t_min, rounding monotonicity
// freezes the trajectory and the reference's final t equals t_min.
__device__ __forceinline__ float bisect_t(float Hraw, float Lraw) {
    const float H = __fmul_rn(0.5f, Hraw);   // Xs = 0.5*X, exact & monotone
    const float L = __fmul_rn(0.5f, Lraw);
    const float p = (float)(1.0 / 4095.0);
    float t_min = H - 1.0f;                  // m - 1
    float t_max = H - 0.015625f;             // m - 4096^(1-1.5)
    float diff  = t_max - t_min;
    float t     = t_min;
    if (H - L < 0.998f) {
        // Common case: mask <=> (t < L). FADD + FSEL per iteration.
        #pragma unroll 1
        for (int it = 0; it < 50; it++) {
            diff *= 0.5f;
            t = t_min + diff;
            if (t == t_min) break;           // frozen: final t == t_min
            t_min = (t < L) ? t : t_min;
        }
    } else {
        #pragma unroll 1
        for (int it = 0; it < 50; it++) {
            diff *= 0.5f;
            t = t_min + diff;
            if (t == t_min) break;
            bool mask;
            if (t < L) {
                mask = true;                 // >=2 positive terms -> sum >= 1.95
            } else {
                float u1 = H - t;
                mask = (u1 >= 0.999f) ? (powf(u1, p) >= 1.0f) : false;
            }
            if (mask) t_min = t;
        }
    }
    return t;
}

__global__ __launch_bounds__(TPB, 8)
void entmax_bisect_kernel(const float* __restrict__ X, float* __restrict__ Y) {
    const int tid  = threadIdx.x;
    const int lane = tid & 31;
    const int wid  = tid >> 5;
    const size_t base = (size_t)blockIdx.x * D;

    __shared__ float s_h[NWARP], s_l[NWARP];
    __shared__ float s_t;
    __shared__ float s_S;

    const float4* Xv = reinterpret_cast<const float4*>(X + base);
    float4*       Yv = reinterpret_cast<float4*>(Y + base);

    if (tid == 0) s_S = 0.0f;                // ordered before atomics by b1+b2

    // ---- Pass 1: load 16 values, TREE top-2 fold (short critical path) ----
    float hi, lo;
    {
        float4 f0 = Xv[tid];
        float4 f1 = Xv[TPB + tid];
        float4 f2 = Xv[2 * TPB + tid];
        float4 f3 = Xv[3 * TPB + tid];

        // per-quad top-2 (depth 3, independent across quads)
        float h0a = fmaxf(f0.x, f0.y), l0a = fminf(f0.x, f0.y);
        float h0b = fmaxf(f0.z, f0.w), l0b = fminf(f0.z, f0.w);
        float h0 = fmaxf(h0a, h0b), l0 = fmaxf(fminf(h0a, h0b), fmaxf(l0a, l0b));

        float h1a = fmaxf(f1.x, f1.y), l1a = fminf(f1.x, f1.y);
        float h1b = fmaxf(f1.z, f1.w), l1b = fminf(f1.z, f1.w);
        float h1 = fmaxf(h1a, h1b), l1 = fmaxf(fminf(h1a, h1b), fmaxf(l1a, l1b));

        float h2a = fmaxf(f2.x, f2.y), l2a = fminf(f2.x, f2.y);
        float h2b = fmaxf(f2.z, f2.w), l2b = fminf(f2.z, f2.w);
        float h2 = fmaxf(h2a, h2b), l2 = fmaxf(fminf(h2a, h2b), fmaxf(l2a, l2b));

        float h3a = fmaxf(f3.x, f3.y), l3a = fminf(f3.x, f3.y);
        float h3b = fmaxf(f3.z, f3.w), l3b = fminf(f3.z, f3.w);
        float h3 = fmaxf(h3a, h3b), l3 = fmaxf(fminf(h3a, h3b), fmaxf(l3a, l3b));

        // quad merges (depth 2)
        merge2(h1, l1, h0, l0);
        merge2(h3, l3, h2, l2);
        merge2(h2, l2, h0, l0);
        hi = h0; lo = l0;
    }
    const float thi = hi;                    // per-thread raw max

    // ---- Warp butterfly top-2 (sm_103 has no fp32 redux) ----
    #pragma unroll
    for (int off = 16; off > 0; off >>= 1) {
        float oh = __shfl_xor_sync(0xffffffffu, hi, off);
        float ol = __shfl_xor_sync(0xffffffffu, lo, off);
        float nh = fmaxf(hi, oh);
        lo = fmaxf(fmaxf(lo, ol), fminf(hi, oh));
        hi = nh;
    }
    if (lane == 0) { s_h[wid] = hi; s_l[wid] = lo; }
    __syncthreads();                                      // b1

    // ---- All threads: combine 8 warps' top-2 (16 LDS, short tree) ----
    float Hb = s_h[0], Lb = s_l[0];
    {
        float h1 = s_h[1], l1 = s_l[1];
        float h2 = s_h[2], l2 = s_l[2];
        float h3 = s_h[3], l3 = s_l[3];
        float h4 = s_h[4], l4 = s_l[4];
        float h5 = s_h[5], l5 = s_l[5];
        float h6 = s_h[6], l6 = s_l[6];
        float h7 = s_h[7], l7 = s_l[7];
        merge2(h1, l1, Hb, Lb);
        merge2(h3, l3, h2, l2);
        merge2(h5, l5, h4, l4);
        merge2(h7, l7, h6, l6);
        merge2(h2, l2, Hb, Lb);
        merge2(h6, l6, h4, l4);
        merge2(h4, l4, Hb, Lb);
    }

    // ---- Sure-cold: t_final >= min(Ls, Hs - 0.015625) - 2*diff_final.
    // Threads below that (fat margin) output only zeros; store NOW so the
    // write stream overlaps the bisection bubble. ----
    const float Hs   = __fmul_rn(0.5f, Hb);
    const float Ls   = __fmul_rn(0.5f, Lb);
    const float thr  = fminf(Ls, Hs - 0.015625f) - 2e-5f;
    const float myXs = __fmul_rn(0.5f, thi);
    const bool sure_cold = (myXs < thr);

    const float4 zero4 = make_float4(0.0f, 0.0f, 0.0f, 0.0f);
    if (sure_cold) {
        __stcs(Yv + tid,           zero4);
        __stcs(Yv + TPB + tid,     zero4);
        __stcs(Yv + 2 * TPB + tid, zero4);
        __stcs(Yv + 3 * TPB + tid, zero4);
    }

    // ---- Thread 0: scalar bisection (zero stores above already in flight) ----
    if (tid == 0) s_t = bisect_t(Hb, Lb);
    __syncthreads();                                      // b2

    const float t = s_t;
    const float p = (float)(1.0 / 4095.0);
    const bool hot = (!sure_cold) && (myXs > t);

    // ---- Pass 2 (hot threads, ~1-3 per row): re-read, atomic-add z sum ----
    if (hot) {
        float sum = 0.0f;
        #pragma unroll
        for (int k = 0; k < 4; k++) {
            float4 g = reload4(Xv + k * TPB + tid);
            float u;
            u = __fmul_rn(0.5f, g.x) - t; if (u > 0.0f) sum += powf(u, p);
            u = __fmul_rn(0.5f, g.y) - t; if (u > 0.0f) sum += powf(u, p);
            u = __fmul_rn(0.5f, g.z) - t; if (u > 0.0f) sum += powf(u, p);
            u = __fmul_rn(0.5f, g.w) - t; if (u > 0.0f) sum += powf(u, p);
        }
        atomicAdd(&s_S, sum);
    }
    __syncthreads();                                      // b3

    const float S = s_S;

    // ---- Epilogue: hot threads write spans; unsure-cold write zeros ----
    if (hot) {
        const float rinv = 1.0f / S;                      // S > 0 always
        #pragma unroll
        for (int k = 0; k < 4; k++) {
            float4 g = reload4(Xv + k * TPB + tid);       // L1 hit
            float4 o = zero4;
            float u;
            u = __fmul_rn(0.5f, g.x) - t; if (u > 0.0f) o.x = powf(u, p) * rinv;
            u = __fmul_rn(0.5f, g.y) - t; if (u > 0.0f) o.y = powf(u, p) * rinv;
            u = __fmul_rn(0.5f, g.z) - t; if (u > 0.0f) o.z = powf(u, p) * rinv;
            u = __fmul_rn(0.5f, g.w) - t; if (u > 0.0f) o.w = powf(u, p) * rinv;
            __stcs(Yv + k * TPB + tid, o);
        }
    } else if (!sure_cold) {
        __stcs(Yv + tid,           zero4);
        __stcs(Yv + TPB + tid,     zero4);
        __stcs(Yv + 2 * TPB + tid, zero4);
        __stcs(Yv + 3 * TPB + tid, zero4);
    }
}

extern "C" void kernel_launch(void* const* d_in, const int* in_sizes, int n_in,
                              void* d_out, int out_size) {
    const float* X = (const float*)d_in[0];
    float* Y = (float*)d_out;
    const int rows = in_sizes[0] / D;                     // 16384
    entmax_bisect_kernel<<<rows, TPB>>>(X, Y);
}

// round 13
// speedup vs baseline: 1.3414x; 1.0056x over previous
#include <cuda_runtime.h>

#define D     4096
#define TPB   256
#define NWARP (TPB / 32)

// Forced re-read (asm volatile so the compiler cannot CSE it with the pass-1
// loads and keep 16 registers alive across barriers).
__device__ __forceinline__ float4 reload4(const float4* p) {
    float4 v;
    asm volatile("ld.global.ca.v4.f32 {%0,%1,%2,%3}, [%4];"
                 : "=f"(v.x), "=f"(v.y), "=f"(v.z), "=f"(v.w)
                 : "l"(p));
    return v;
}

// Exact top-2 merge of two (hi,lo) pairs (handles duplicates correctly):
// merged hi = max(h1,h2); merged lo = max(min(h1,h2), max(l1,l2)).
__device__ __forceinline__ void merge2(float h2, float l2, float& hi, float& lo) {
    float nh = fmaxf(hi, h2);
    lo = fmaxf(fminf(hi, h2), fmaxf(lo, l2));
    hi = nh;
}

// 50-step bisection, fp32 op-for-op identical to the reference trajectory.
// mask = (sum(Z)-1 >= 0). With p = 1/4095, u^p in [0.975, 1] for every
// positive fp32 u, so mask <=> count(Xs_j > t) >= 2, except count==1 where
// sum = powf(u1,p) can round to >= 1.0f only for u1 within ~1e-4 of 1.
// That edge needs u1 = H - t >= 0.999 while t >= L, i.e. H - L >= 0.999;
// when H - L < 0.998 the loop is provably pure "t < L" -> branchless form.
// Early exit: once t = t_min + diff rounds to t_min, rounding monotonicity
// freezes the trajectory and the reference's final t equals t_min.
__device__ __forceinline__ float bisect_t(float Hraw, float Lraw) {
    const float H = __fmul_rn(0.5f, Hraw);   // Xs = 0.5*X, exact & monotone
    const float L = __fmul_rn(0.5f, Lraw);
    const float p = (float)(1.0 / 4095.0);
    float t_min = H - 1.0f;                  // m - 1
    float t_max = H - 0.015625f;             // m - 4096^(1-1.5)
    float diff  = t_max - t_min;
    float t     = t_min;
    if (H - L < 0.998f) {
        // Common case: mask <=> (t < L). FADD + FSEL per iteration.
        #pragma unroll 1
        for (int it = 0; it < 50; it++) {
            diff *= 0.5f;
            t = t_min + diff;
            if (t == t_min) break;           // frozen: final t == t_min
            t_min = (t < L) ? t : t_min;
        }
    } else {
        #pragma unroll 1
        for (int it = 0; it < 50; it++) {
            diff *= 0.5f;
            t = t_min + diff;
            if (t == t_min) break;
            bool mask;
            if (t < L) {
                mask = true;                 // >=2 positive terms -> sum >= 1.95
            } else {
                float u1 = H - t;
                mask = (u1 >= 0.999f) ? (powf(u1, p) >= 1.0f) : false;
            }
            if (mask) t_min = t;
        }
    }
    return t;
}

__global__ __launch_bounds__(TPB, 8)
void entmax_bisect_kernel(const float* __restrict__ X, float* __restrict__ Y) {
    const int tid  = threadIdx.x;
    const int lane = tid & 31;
    const int wid  = tid >> 5;
    const size_t base = (size_t)blockIdx.x * D;

    __shared__ float s_h[NWARP], s_l[NWARP];
    __shared__ float s_t;
    __shared__ float s_S;

    const float4* Xv = reinterpret_cast<const float4*>(X + base);
    float4*       Yv = reinterpret_cast<float4*>(Y + base);

    if (tid == 0) s_S = 0.0f;                // ordered before atomics by b1+b2

    // ---- Pass 1: load 16 values, TREE top-2 fold (short critical path) ----
    float hi, lo;
    {
        float4 f0 = Xv[tid];
        float4 f1 = Xv[TPB + tid];
        float4 f2 = Xv[2 * TPB + tid];
        float4 f3 = Xv[3 * TPB + tid];

        // per-quad top-2 (depth 3, independent across quads)
        float h0a = fmaxf(f0.x, f0.y), l0a = fminf(f0.x, f0.y);
        float h0b = fmaxf(f0.z, f0.w), l0b = fminf(f0.z, f0.w);
        float h0 = fmaxf(h0a, h0b), l0 = fmaxf(fminf(h0a, h0b), fmaxf(l0a, l0b));

        float h1a = fmaxf(f1.x, f1.y), l1a = fminf(f1.x, f1.y);
        float h1b = fmaxf(f1.z, f1.w), l1b = fminf(f1.z, f1.w);
        float h1 = fmaxf(h1a, h1b), l1 = fmaxf(fminf(h1a, h1b), fmaxf(l1a, l1b));

        float h2a = fmaxf(f2.x, f2.y), l2a = fminf(f2.x, f2.y);
        float h2b = fmaxf(f2.z, f2.w), l2b = fminf(f2.z, f2.w);
        float h2 = fmaxf(h2a, h2b), l2 = fmaxf(fminf(h2a, h2b), fmaxf(l2a, l2b));

        float h3a = fmaxf(f3.x, f3.y), l3a = fminf(f3.x, f3.y);
        float h3b = fmaxf(f3.z, f3.w), l3b = fminf(f3.z, f3.w);
        float h3 = fmaxf(h3a, h3b), l3 = fmaxf(fminf(h3a, h3b), fmaxf(l3a, l3b));

        // quad merges (depth 2)
        merge2(h1, l1, h0, l0);
        merge2(h3, l3, h2, l2);
        merge2(h2, l2, h0, l0);
        hi = h0; lo = l0;
    }
    const float thi = hi;                    // per-thread raw max

    // ---- Warp butterfly top-2 (sm_103 has no fp32 redux) ----
    #pragma unroll
    for (int off = 16; off > 0; off >>= 1) {
        float oh = __shfl_xor_sync(0xffffffffu, hi, off);
        float ol = __shfl_xor_sync(0xffffffffu, lo, off);
        float nh = fmaxf(hi, oh);
        lo = fmaxf(fmaxf(lo, ol), fminf(hi, oh));
        hi = nh;
    }
    // hi/lo now hold the WARP top-2 in every lane.

    // ---- WARP-LOCAL sure-cold test: the warp's top-2 dominate no element of
    // this warp, and warp top-2 <= row top-2 elementwise, so
    //   thr_w = min(l_w/2, h_w/2 - 1/64) - 2e-5  <=  thr_row  <=  t_final.
    // Threads below thr_w provably output only zeros -> store NOW, before the
    // first barrier, overlapping combine + bisection + everything serial.
    // At most the 1-2 lanes holding the warp's top-2 defer to the epilogue. ----
    const float myXs = __fmul_rn(0.5f, thi);
    const float thr_w = fminf(__fmul_rn(0.5f, lo),
                              __fmul_rn(0.5f, hi) - 0.015625f) - 2e-5f;
    const bool early_cold = (myXs < thr_w);

    const float4 zero4 = make_float4(0.0f, 0.0f, 0.0f, 0.0f);
    if (early_cold) {
        __stcs(Yv + tid,           zero4);
        __stcs(Yv + TPB + tid,     zero4);
        __stcs(Yv + 2 * TPB + tid, zero4);
        __stcs(Yv + 3 * TPB + tid, zero4);
    }

    if (lane == 0) { s_h[wid] = hi; s_l[wid] = lo; }
    __syncthreads();                                      // b1

    // ---- Thread 0 only: combine 8 warps' top-2 (tree) + scalar bisection ----
    if (tid == 0) {
        float Hb = s_h[0], Lb = s_l[0];
        float h1 = s_h[1], l1 = s_l[1];
        float h2 = s_h[2], l2 = s_l[2];
        float h3 = s_h[3], l3 = s_l[3];
        float h4 = s_h[4], l4 = s_l[4];
        float h5 = s_h[5], l5 = s_l[5];
        float h6 = s_h[6], l6 = s_l[6];
        float h7 = s_h[7], l7 = s_l[7];
        merge2(h1, l1, Hb, Lb);
        merge2(h3, l3, h2, l2);
        merge2(h5, l5, h4, l4);
        merge2(h7, l7, h6, l6);
        merge2(h2, l2, Hb, Lb);
        merge2(h6, l6, h4, l4);
        merge2(h4, l4, Hb, Lb);
        s_t = bisect_t(Hb, Lb);
    }
    __syncthreads();                                      // b2

    const float t = s_t;
    const float p = (float)(1.0 / 4095.0);
    // early_cold threads have myXs < thr_w <= t, so they are never hot.
    const bool hot = (myXs > t);

    // ---- Pass 2 (hot threads, ~1-3 per row): re-read, atomic-add z sum ----
    if (hot) {
        float sum = 0.0f;
        #pragma unroll
        for (int k = 0; k < 4; k++) {
            float4 g = reload4(Xv + k * TPB + tid);
            float u;
            u = __fmul_rn(0.5f, g.x) - t; if (u > 0.0f) sum += powf(u, p);
            u = __fmul_rn(0.5f, g.y) - t; if (u > 0.0f) sum += powf(u, p);
            u = __fmul_rn(0.5f, g.z) - t; if (u > 0.0f) sum += powf(u, p);
            u = __fmul_rn(0.5f, g.w) - t; if (u > 0.0f) sum += powf(u, p);
        }
        atomicAdd(&s_S, sum);
    }
    __syncthreads();                                      // b3

    const float S = s_S;

    // ---- Epilogue: hot threads write spans; deferred-cold write zeros ----
    if (hot) {
        const float rinv = 1.0f / S;                      // S > 0 always
        #pragma unroll
        for (int k = 0; k < 4; k++) {
            float4 g = reload4(Xv + k * TPB + tid);       // L1 hit
            float4 o = zero4;
            float u;
            u = __fmul_rn(0.5f, g.x) - t; if (u > 0.0f) o.x = powf(u, p) * rinv;
            u = __fmul_rn(0.5f, g.y) - t; if (u > 0.0f) o.y = powf(u, p) * rinv;
            u = __fmul_rn(0.5f, g.z) - t; if (u > 0.0f) o.z = powf(u, p) * rinv;
            u = __fmul_rn(0.5f, g.w) - t; if (u > 0.0f) o.w = powf(u, p) * rinv;
            __stcs(Yv + k * TPB + tid, o);
        }
    } else if (!early_cold) {
        __stcs(Yv + tid,           zero4);
        __stcs(Yv + TPB + tid,     zero4);
        __stcs(Yv + 2 * TPB + tid, zero4);
        __stcs(Yv + 3 * TPB + tid, zero4);
    }
}

extern "C" void kernel_launch(void* const* d_in, const int* in_sizes, int n_in,
                              void* d_out, int out_size) {
    const float* X = (const float*)d_in[0];
    float* Y = (float*)d_out;
    const int rows = in_sizes[0] / D;                     // 16384
    entmax_bisect_kernel<<<rows, TPB>>>(X, Y);
}